// round 11
// baseline (speedup 1.0000x reference)
#include <cuda_runtime.h>
#include <math.h>

// DTW loss, LEN=2048, squared-difference cost, out = sqrt(DTW[N-1][N-1]).
//
// Bidirectional decomposition (exact): any monotone path crosses row
// 1023 -> 1024 exactly once, so
//   DTW^2 = min_j ( F[1023][j] + min(B[1024][j], B[1024][j+1]) )
// F = forward DP rows 0..1023; B = backward DP on (reverse(x), reverse(y)):
// B[1024][j] = G[1023][2047-j].  One kernel, grid=2 (CTA0=F, CTA1=G).
//
// Systolic column DP, BARRIER-FREE: 128 threads, 16 cols/thread, 4 rows/step.
// Thread schedule offset o = tid + wid*EXTRA (extra inter-warp skew so the
// cross-warp handoff has slack); at step s a thread processes row block
// b = s - o (clamped; out-of-range blocks run on all-INF state == virtual
// border, fma(d,d,INF)=INF, d finite => no NaN).
// Handoff of the 4 boundary values per step:
//   - within a warp: __shfl_up of the previous step's published float4
//   - across warps:  smem ring (one slot per step, no wrap) + per-warp
//     progress counter with ld.acquire.cta / st.release.cta. Warp w only
//     waits on warp w-1 (acyclic; warp 0 never waits). Consumer at step s
//     reads slot s-1-EXTRA, written EXTRA+1 producer-steps earlier -> the
//     acquire poll passes first try in steady state.
// Last CTA to finish fuses the min-plus combine (atomic counter + fences).
//
// Per-cell (4 instr, fma/alu pipes balanced):
//   d = xi + (-y_j); m = fmin(up, dg); mm = fmin(m, left); v = fma(d,d,mm)

#define LEN   2048
#define HALF  1024
#define NT    128
#define NW    (NT / 32)            // 4 warps
#define CPT   16                   // columns per thread
#define RPS   4                    // rows per step
#define NBLK  (HALF / RPS)         // 256
#define EXTRA 4                    // extra skew per warp boundary
#define MAXO  (NT - 1 + (NW - 1) * EXTRA)   // 139
#define STEPS (NBLK + MAXO)        // 395

__device__ float g_rows[2][LEN];   // [0]=F row 1023, [1]=G row 1023 (reversed idx)
__device__ int   g_ctr = 0;        // completion counter (reset each launch)

__device__ __forceinline__ unsigned smem_u32(const void* p) {
    return (unsigned)__cvta_generic_to_shared(p);
}
__device__ __forceinline__ int ld_acq(const int* p) {
    int v;
    asm volatile("ld.acquire.cta.shared.b32 %0, [%1];"
                 : "=r"(v) : "r"(smem_u32(p)) : "memory");
    return v;
}
__device__ __forceinline__ void st_rel(int* p, int v) {
    asm volatile("st.release.cta.shared.b32 [%0], %1;"
                 :: "r"(smem_u32(p)), "r"(v) : "memory");
}

__global__ __launch_bounds__(NT, 1)
void dtw_fused_kernel(const float* __restrict__ x,
                      const float* __restrict__ y,
                      float* __restrict__ out)
{
    __shared__ float4 xs4[HALF / 4];          // this half's x rows (4 KB)
    __shared__ float4 ring[NW - 1][STEPS];    // cross-warp boundary values (~19 KB)
    __shared__ int    prog[NW - 1];           // producer progress (last step written)
    __shared__ float  red[NW];
    __shared__ int    amLast;

    const int tid  = threadIdx.x;
    const int lane = tid & 31;
    const int wid  = tid >> 5;
    const int o    = tid + wid * EXTRA;       // systolic schedule offset
    const int dir  = blockIdx.x;              // 0 = forward half, 1 = reversed
    const float INF = __int_as_float(0x7f800000);
    const float4 INF4 = make_float4(INF, INF, INF, INF);

    // Preload x rows for this half (forward: x[0..1023]; reversed: x[2047..1024]).
    {
        float* xs = reinterpret_cast<float*>(xs4);
        if (dir == 0) {
            for (int i = tid; i < HALF; i += NT) xs[i] = x[i];
        } else {
            for (int i = tid; i < HALF; i += NT) xs[i] = x[LEN - 1 - i];
        }
    }
    if (tid < NW - 1) prog[tid] = -1;

    // Column-strip state in registers (reversed y for the backward half).
    float negY[CPT], up[CPT];
#pragma unroll
    for (int j = 0; j < CPT; ++j) {
        const int col = tid * CPT + j;
        negY[j] = -((dir == 0) ? y[col] : y[LEN - 1 - col]);
        up[j]   = INF;                   // virtual row -1
    }

    // diag entering first row of the next block: v[4b-1][16t-1].
    // Thread 0, block 0: corner (-1,-1) = 0. Otherwise +inf.
    float diag = (tid == 0) ? 0.0f : INF;

    float* gout = &g_rows[dir][tid * CPT];

    __syncthreads();                     // only barrier: init visibility

    float4 prevPub = INF4;               // my published values from step s-1
    float4 xv = xs4[0];                  // prefetched x rows (bc(s=0)=0)

    // One barrier-free systolic step.
    auto step_body = [&](int s, bool pub) {
        // Boundary values for my 4 rows: lane l gets lane l-1's step s-1
        // publication via shfl; lane 0 gets it from the cross-warp ring.
        float4 L;
        L.x = __shfl_up_sync(0xFFFFFFFFu, prevPub.x, 1);
        L.y = __shfl_up_sync(0xFFFFFFFFu, prevPub.y, 1);
        L.z = __shfl_up_sync(0xFFFFFFFFu, prevPub.z, 1);
        L.w = __shfl_up_sync(0xFFFFFFFFu, prevPub.w, 1);
        if (lane == 0) {
            L = INF4;                    // warp 0: virtual column forever
            const int slot = s - 1 - EXTRA;
            if (wid > 0 && slot >= 0) {
                while (ld_acq(&prog[wid - 1]) < slot) { }
                L = ring[wid - 1][slot];
            }
        }

        const float lx[4] = {L.x, L.y, L.z, L.w};
        const float xr[4] = {xv.x, xv.y, xv.z, xv.w};
        float pb[4];

        float dgen = diag;               // diag entering first row of block
#pragma unroll
        for (int k = 0; k < RPS; ++k) {
            float left = lx[k];
            float dg   = dgen;
            const float xi = xr[k];
#pragma unroll
            for (int j = 0; j < CPT; ++j) {
                const float d  = xi + negY[j];     // FADD
                const float m  = fminf(up[j], dg); // off-chain FMNMX
                const float mm = fminf(m, left);   // chain FMNMX
                const float v  = fmaf(d, d, mm);   // chain FFMA
                dg    = up[j];                     // reg rename (free)
                up[j] = v;
                left  = v;
            }
            pb[k] = left;
            dgen  = lx[k];
        }
        diag = lx[3];

        const float4 pubv = make_float4(pb[0], pb[1], pb[2], pb[3]);
        // Cross-warp publish: lane 31 of warps 0..NW-2 (data, then release).
        if (lane == 31 && wid < NW - 1) {
            ring[wid][s] = pubv;
            st_rel(&prog[wid], s);
        }
        prevPub = pubv;

        // Prefetch next step's x rows.
        const int bn = min(max(s + 1 - o, 0), NBLK - 1);
        xv = xs4[bn];

        if (pub) {
            // Publish my final row exactly once (before later garbage).
            if (s - o == NBLK - 1) {
#pragma unroll
                for (int j = 0; j < CPT; ++j) gout[j] = up[j];
            }
        }
    };

    // Phase A: s in [0, NBLK-1) — no thread can publish yet.
    for (int s = 0; s < NBLK - 1; ++s)  step_body(s, false);
    // Phase B: s in [NBLK-1, STEPS) — guarded publish.
    for (int s = NBLK - 1; s < STEPS; ++s) step_body(s, true);

    // ── fused combine: last CTA to finish does the min-plus join ──
    __threadfence();                     // release g_rows writes
    __syncthreads();                     // all warps done before counting
    if (tid == 0) {
        int old = atomicAdd(&g_ctr, 1);
        amLast = (old == 1);
    }
    __syncthreads();
    if (!amLast) return;
    __threadfence();                     // acquire: order reads after atomic

    // term_j = F[1023][j] + min(B[1024][j], B[1024][j+1]),
    // B[1024][j] = g_rows[1][LEN-1-j], B[1024][LEN] = +inf.
    float m = INF;
#pragma unroll
    for (int k = 0; k < LEN / NT; ++k) {
        const int j = tid + k * NT;
        const float F  = g_rows[0][j];
        const float B0 = g_rows[1][LEN - 1 - j];
        const float B1 = (j + 1 < LEN) ? g_rows[1][LEN - 2 - j] : INF;
        m = fminf(m, F + fminf(B0, B1));
    }
#pragma unroll
    for (int off = 16; off; off >>= 1)
        m = fminf(m, __shfl_xor_sync(0xFFFFFFFFu, m, off));
    if (lane == 0) red[wid] = m;
    __syncthreads();
    if (tid == 0) {
        float v = fminf(fminf(red[0], red[1]), fminf(red[2], red[3]));
        out[0] = sqrtf(v);
        g_ctr  = 0;                      // reset for next graph replay
    }
}

extern "C" void kernel_launch(void* const* d_in, const int* in_sizes, int n_in,
                              void* d_out, int out_size)
{
    (void)in_sizes; (void)n_in; (void)out_size;
    const float* x = (const float*)d_in[0];
    const float* y = (const float*)d_in[1];
    float* out = (float*)d_out;
    dtw_fused_kernel<<<2, NT>>>(x, y, out);
}